// round 4
// baseline (speedup 1.0000x reference)
#include <cuda_runtime.h>
#include <cuda_bf16.h>
#include <cstdint>
#include <cstddef>

#define NB 64
#define NS 512
#define NE 128
#define NH 256
#define NG 1024      // 4*NH
#define NT 9
#define NM 32768     // NB*NS

// ---------------- packed fp32x2 helpers (Blackwell FFMA2 path) ---------------
#define FMA2(d, a, b) \
    asm("fma.rn.f32x2 %0, %1, %2, %0;" : "+l"(d) : "l"(a), "l"(b))
#define PACKDUP(d, x) \
    asm("mov.b64 %0, {%1, %1};" : "=l"(d) : "r"(__float_as_int(x)))
__device__ __forceinline__ float f2_lo(uint64_t v) {
    return __int_as_float((int)(v & 0xffffffffull));
}
__device__ __forceinline__ float f2_hi(uint64_t v) {
    return __int_as_float((int)(v >> 32));
}

// ---------------- cluster / DSMEM helpers ------------------------------------
__device__ __forceinline__ uint32_t mapa_sh(uint32_t local, uint32_t rank) {
    uint32_t r;
    asm("mapa.shared::cluster.u32 %0, %1, %2;" : "=r"(r) : "r"(local), "r"(rank));
    return r;
}
__device__ __forceinline__ void sts_cluster_u64(uint32_t addr, uint64_t v) {
    asm volatile("st.shared::cluster.u64 [%0], %1;" :: "r"(addr), "l"(v) : "memory");
}
__device__ __forceinline__ void cluster_sync_() {
    asm volatile("barrier.cluster.arrive.aligned;" ::: "memory");
    asm volatile("barrier.cluster.wait.aligned;" ::: "memory");
}

// ---------------- scratch: device globals (no allocation allowed) -----------
__device__ float g_xz[(size_t)2 * NM * NG];      // 256 MB  input projections
__device__ float g_h [(size_t)NM * 2 * NH];      // 64 MB   concat h (fwd|bwd)
__device__ int   g_lens[NB];

// ---------------- math helpers ----------------------------------------------
__device__ __forceinline__ float sigf(float x) { return 1.f / (1.f + __expf(-x)); }
__device__ __forceinline__ float tanhf_fast(float x) {
    float e = __expf(2.f * fabsf(x));
    float t = 1.f - 2.f / (e + 1.f);
    return copysignf(t, x);
}

// ---------------- text lens --------------------------------------------------
__global__ void k_lens(const int* __restrict__ text) {
    int b = blockIdx.x;
    int c = 0;
    for (int i = threadIdx.x; i < NS; i += 128) c += (text[b * NS + i] != 0);
    #pragma unroll
    for (int o = 16; o; o >>= 1) c += __shfl_xor_sync(0xffffffffu, c, o);
    __shared__ int ws[4];
    if ((threadIdx.x & 31) == 0) ws[threadIdx.x >> 5] = c;
    __syncthreads();
    if (threadIdx.x == 0) g_lens[b] = ws[0] + ws[1] + ws[2] + ws[3];
}

// ---------------- xz = emb[text] @ W + b  (both dirs), FFMA2 ----------------
// grid (512 mtiles, 16 ntiles, 2 dirs), 256 threads, 64x64 tile, K=128
__global__ __launch_bounds__(256) void k_xz(
    const int* __restrict__ text, const float* __restrict__ emb,
    const float* __restrict__ Wf, const float* __restrict__ bf,
    const float* __restrict__ Wb, const float* __restrict__ bb)
{
    extern __shared__ float sm[];
    float* As = sm;               // 64 x 132
    float* Bs = sm + 64 * 132;    // 128 x 68
    __shared__ int tok[64];

    int t = threadIdx.x;
    int m0 = blockIdx.x * 64, n0 = blockIdx.y * 64, dir = blockIdx.z;
    const float* W    = dir ? Wb : Wf;
    const float* bias = dir ? bb : bf;

    if (t < 64) tok[t] = text[m0 + t];
    __syncthreads();

    #pragma unroll
    for (int i = 0; i < 8; i++) {
        int idx = t + i * 256;
        int r = idx >> 5, c4 = idx & 31;
        float4 v = reinterpret_cast<const float4*>(emb + (size_t)tok[r] * NE)[c4];
        *reinterpret_cast<float4*>(&As[r * 132 + c4 * 4]) = v;
    }
    #pragma unroll
    for (int i = 0; i < 32; i++) {
        int idx = t + i * 256;
        int k = idx >> 6, n = idx & 63;
        Bs[k * 68 + n] = W[(size_t)k * NG + n0 + n];
    }
    __syncthreads();

    int tx = t & 15, ty = t >> 4;
    uint64_t acc[4][2];
    #pragma unroll
    for (int j = 0; j < 4; j++) { acc[j][0] = 0ull; acc[j][1] = 0ull; }

    #pragma unroll 4
    for (int k0 = 0; k0 < 128; k0 += 4) {
        float av[4][4];
        #pragma unroll
        for (int j = 0; j < 4; j++)
            *reinterpret_cast<float4*>(av[j]) =
                *reinterpret_cast<const float4*>(&As[(ty * 4 + j) * 132 + k0]);
        #pragma unroll
        for (int kk = 0; kk < 4; kk++) {
            ulonglong2 b2 = *reinterpret_cast<const ulonglong2*>(&Bs[(k0 + kk) * 68 + tx * 4]);
            #pragma unroll
            for (int j = 0; j < 4; j++) {
                uint64_t ad; PACKDUP(ad, av[j][kk]);
                FMA2(acc[j][0], ad, b2.x);
                FMA2(acc[j][1], ad, b2.y);
            }
        }
    }

    float4 bv = *reinterpret_cast<const float4*>(bias + n0 + tx * 4);
    #pragma unroll
    for (int j = 0; j < 4; j++) {
        int m = m0 + ty * 4 + j;
        size_t base = ((size_t)dir * NM + m) * NG + n0 + tx * 4;
        float4 o;
        o.x = f2_lo(acc[j][0]) + bv.x;
        o.y = f2_hi(acc[j][0]) + bv.y;
        o.z = f2_lo(acc[j][1]) + bv.z;
        o.w = f2_hi(acc[j][1]) + bv.w;
        *reinterpret_cast<float4*>(&g_xz[base]) = o;
    }
}

// ---------------- persistent LSTM: 8-CTA cluster + DSMEM h exchange ----------
// grid (8 colblocks, 8 batch-slices, 2 dirs); cluster = the 8 colblocks.
// smem 192KB -> 1 CTA/SM. h pushed to peers via st.shared::cluster, double-
// buffered, one cluster.sync per step.
__global__ __launch_bounds__(256) __cluster_dims__(8, 1, 1)
void k_lstm(const float* __restrict__ Uf, const float* __restrict__ Ub)
{
    extern __shared__ float sm[];
    float*    Us   = sm;                               // [256 k][128 cc]  128KB
    uint64_t* hsd0 = (uint64_t*)(sm + 32768);          // [8 bi][256 k] dup 16KB
    uint64_t* hsd1 = hsd0 + 2048;                      // second buffer    16KB
    float*    zp   = sm + 32768 + 8192;                // [8 kq][8 bi][128] 32KB

    const int t   = threadIdx.x;
    const int cb  = blockIdx.x, bsl = blockIdx.y, dir = blockIdx.z;
    const int j0  = cb * 32, b0 = bsl * 8;
    const float* U = dir ? Ub : Uf;

    // U slice, k-major: Us[k][cc], cc -> gate col (cc/32)*256 + j0 + cc%32
    for (int i = t; i < 128 * 256; i += 256) {
        int cc = i & 127, k = i >> 7;
        int zc = ((cc >> 5) << 8) + j0 + (cc & 31);
        Us[k * 128 + cc] = U[(size_t)k * NG + zc];
    }
    for (int i = t; i < 8 * 256; i += 256) hsd0[i] = 0ull;

    // gate-phase mapping: thread (gb, gj) owns col j0+gj of batch b0+gb
    const int gb = t >> 5, gj = t & 31;
    // GEMM mapping: warp = 32-k slice, lanes x 4cc cover 128 cc
    const int kq = t >> 5, ccg = t & 31;
    const int kbase = kq * 32, cc0 = ccg * 4;

    // DSMEM byte offset of this gate thread's h slot in peers' buffers
    const uint32_t hoff = (uint32_t)((gb * 256 + j0 + gj) * 8);
    const uint32_t hsd0_sh = (uint32_t)__cvta_generic_to_shared(hsd0);
    const uint32_t hsd1_sh = (uint32_t)__cvta_generic_to_shared(hsd1);

    float c_reg = 0.f;
    __syncthreads();

    for (int s = 0; s < NS; s++) {
        const int tm = dir ? (NS - 1 - s) : s;
        const uint64_t* hcur = (s & 1) ? hsd1 : hsd0;
        const uint32_t  hnxt_sh = ((s & 1) ? hsd0_sh : hsd1_sh) + hoff;

        // prefetch xz for the gate phase (covered by GEMM latency)
        const float* xzp = g_xz +
            (((size_t)dir * NM + (size_t)(b0 + gb) * NS + tm) * NG + j0 + gj);
        float x0 = xzp[0], x1 = xzp[256], x2 = xzp[512], x3 = xzp[768];

        // ---- GEMM: 8 batches x 4 cc over this warp's 32-k slice ----------
        uint64_t acc[8][2];
        #pragma unroll
        for (int bi = 0; bi < 8; bi++) { acc[bi][0] = 0ull; acc[bi][1] = 0ull; }

        #pragma unroll 8
        for (int kk = 0; kk < 32; kk += 2) {
            const int k = kbase + kk;
            ulonglong2 ua = *reinterpret_cast<const ulonglong2*>(Us + k * 128 + cc0);
            ulonglong2 ub = *reinterpret_cast<const ulonglong2*>(Us + (k + 1) * 128 + cc0);
            #pragma unroll
            for (int bi = 0; bi < 8; bi++) {
                ulonglong2 hd = *reinterpret_cast<const ulonglong2*>(hcur + bi * 256 + k);
                FMA2(acc[bi][0], hd.x, ua.x);
                FMA2(acc[bi][1], hd.x, ua.y);
                FMA2(acc[bi][0], hd.y, ub.x);
                FMA2(acc[bi][1], hd.y, ub.y);
            }
        }
        #pragma unroll
        for (int bi = 0; bi < 8; bi++) {
            float4 v;
            v.x = f2_lo(acc[bi][0]); v.y = f2_hi(acc[bi][0]);
            v.z = f2_lo(acc[bi][1]); v.w = f2_hi(acc[bi][1]);
            *reinterpret_cast<float4*>(&zp[kq * 1024 + bi * 128 + cc0]) = v;
        }
        __syncthreads();

        // ---- gates ---------------------------------------------------------
        float zi = x0, zf = x1, zg = x2, zo = x3;
        #pragma unroll
        for (int q = 0; q < 8; q++) {
            const float* z = zp + q * 1024 + gb * 128 + gj;
            zi += z[0]; zf += z[32]; zg += z[64]; zo += z[96];
        }
        float ig = sigf(zi), fg = sigf(zf), gg = tanhf_fast(zg), og = sigf(zo);
        c_reg = fg * c_reg + ig * gg;
        float hv = og * tanhf_fast(c_reg);

        // push dup pair of hv to all 8 cluster CTAs' next-step buffer
        if (s < NS - 1) {
            uint64_t hd; PACKDUP(hd, hv);
            #pragma unroll
            for (int rk = 0; rk < 8; rk++)
                sts_cluster_u64(mapa_sh(hnxt_sh, rk), hd);
        }
        g_h[((size_t)(b0 + gb) * NS + tm) * (2 * NH) + dir * NH + j0 + gj] = hv;
        __syncthreads();   // zp reads done before next step overwrites

        // ---- cluster barrier: peers' pushes land before next GEMM ----------
        if (s < NS - 1) cluster_sync_();
    }
}

// ---------------- logits = h @ W_d + b_d -------------------------------------
__global__ __launch_bounds__(256) void k_logits(const float* __restrict__ Wd,
                                                const float* __restrict__ bd,
                                                float* __restrict__ out)
{
    __shared__ float Wd_s[512 * NT];
    __shared__ float bd_s[NT];
    int t = threadIdx.x;
    for (int i = t; i < 512 * NT; i += 256) Wd_s[i] = Wd[i];
    if (t < NT) bd_s[t] = bd[t];
    __syncthreads();

    int warp = t >> 5, lane = t & 31;
    size_t row = (size_t)blockIdx.x * 8 + warp;
    const float* hr = g_h + row * (2 * NH);

    float acc[NT];
    #pragma unroll
    for (int tg = 0; tg < NT; tg++) acc[tg] = 0.f;

    #pragma unroll
    for (int i = 0; i < 4; i++) {
        int kb = i * 128 + lane * 4;
        float4 h4 = *reinterpret_cast<const float4*>(hr + kb);
        float hvv[4] = {h4.x, h4.y, h4.z, h4.w};
        #pragma unroll
        for (int w = 0; w < 4; w++) {
            int k = kb + w;
            #pragma unroll
            for (int tg = 0; tg < NT; tg++) acc[tg] += hvv[w] * Wd_s[k * NT + tg];
        }
    }
    #pragma unroll
    for (int tg = 0; tg < NT; tg++)
        #pragma unroll
        for (int o = 16; o; o >>= 1) acc[tg] += __shfl_xor_sync(0xffffffffu, acc[tg], o);
    #pragma unroll
    for (int tg = 0; tg < NT; tg++)
        if (lane == tg) out[row * NT + tg] = acc[tg] + bd_s[tg];
}

// ---------------- CRF: sequence score & log-norm -----------------------------
__global__ void k_crf(const int* __restrict__ labels,
                      const float* __restrict__ trans,
                      float* __restrict__ out)
{
    int b = blockIdx.x, lane = threadIdx.x;
    int len = g_lens[b];
    const float* lg = out + (size_t)b * NS * NT;
    const int*   lb = labels + (size_t)b * NS;

    float sc = 0.f;
    for (int t = lane; t < len; t += 32)     sc += lg[t * NT + lb[t]];
    for (int t = lane; t + 1 < len; t += 32) sc += trans[lb[t] * NT + lb[t + 1]];
    #pragma unroll
    for (int o = 16; o; o >>= 1) sc += __shfl_xor_sync(0xffffffffu, sc, o);

    bool act = lane < NT;
    float tr[NT];
    #pragma unroll
    for (int i = 0; i < NT; i++) tr[i] = act ? trans[i * NT + lane] : 0.f;
    float alpha = act ? lg[lane] : -1e30f;

    for (int t = 1; t < len; t++) {
        float lgv = act ? lg[t * NT + lane] : 0.f;
        float v[NT]; float m = -1e30f;
        #pragma unroll
        for (int i = 0; i < NT; i++) {
            float ai = __shfl_sync(0xffffffffu, alpha, i);
            v[i] = ai + tr[i];
            m = fmaxf(m, v[i]);
        }
        float ssum = 0.f;
        #pragma unroll
        for (int i = 0; i < NT; i++) ssum += expf(v[i] - m);
        float na = m + logf(ssum) + lgv;
        if (act) alpha = na;
    }

    float m2 = act ? alpha : -1e30f;
    #pragma unroll
    for (int o = 16; o; o >>= 1) m2 = fmaxf(m2, __shfl_xor_sync(0xffffffffu, m2, o));
    float e = act ? expf(alpha - m2) : 0.f;
    #pragma unroll
    for (int o = 16; o; o >>= 1) e += __shfl_xor_sync(0xffffffffu, e, o);
    float lognorm = m2 + logf(e);

    if (lane == 0) {
        out[(size_t)NM * NT + b]      = (float)len;
        out[(size_t)NM * NT + NB + b] = sc - lognorm;
    }
}

// ---------------- launcher ----------------------------------------------------
extern "C" void kernel_launch(void* const* d_in, const int* in_sizes, int n_in,
                              void* d_out, int out_size)
{
    const int*   text   = (const int*)  d_in[0];
    const int*   labels = (const int*)  d_in[1];
    const float* emb    = (const float*)d_in[2];
    const float* Wf     = (const float*)d_in[3];
    const float* Uf     = (const float*)d_in[4];
    const float* bf     = (const float*)d_in[5];
    const float* Wb     = (const float*)d_in[6];
    const float* Ub     = (const float*)d_in[7];
    const float* bb     = (const float*)d_in[8];
    const float* Wd     = (const float*)d_in[9];
    const float* bd     = (const float*)d_in[10];
    const float* trans  = (const float*)d_in[11];
    float* out = (float*)d_out;

    const int XZ_SMEM   = (64 * 132 + 128 * 68) * 4;            // 68608 B
    const int LSTM_SMEM = (32768 + 2 * 2048 * 2 + 8192) * 4;    // 196608 B
    cudaFuncSetAttribute(k_xz,   cudaFuncAttributeMaxDynamicSharedMemorySize, XZ_SMEM);
    cudaFuncSetAttribute(k_lstm, cudaFuncAttributeMaxDynamicSharedMemorySize, LSTM_SMEM);

    k_lens  <<<NB, 128>>>(text);
    k_xz    <<<dim3(512, 16, 2), 256, XZ_SMEM>>>(text, emb, Wf, bf, Wb, bb);
    k_lstm  <<<dim3(8, 8, 2), 256, LSTM_SMEM>>>(Uf, Ub);
    k_logits<<<NM / 8, 256>>>(Wd, bd, out);
    k_crf   <<<NB, 32>>>(labels, trans, out);
}

// round 5
// speedup vs baseline: 1.2513x; 1.2513x over previous
#include <cuda_runtime.h>
#include <cuda_bf16.h>
#include <cstdint>
#include <cstddef>

#define NB 64
#define NS 512
#define NE 128
#define NH 256
#define NG 1024      // 4*NH
#define NT 9
#define NM 32768     // NB*NS

// ---------------- packed fp32x2 helpers (Blackwell FFMA2 path) ---------------
#define FMA2(d, a, b) \
    asm("fma.rn.f32x2 %0, %1, %2, %0;" : "+l"(d) : "l"(a), "l"(b))
#define PACKDUP(d, x) \
    asm("mov.b64 %0, {%1, %1};" : "=l"(d) : "r"(__float_as_int(x)))
#define PACK2(d, lo, hi) \
    asm("mov.b64 %0, {%1, %2};" : "=l"(d) : "r"(__float_as_int(lo)), "r"(__float_as_int(hi)))
__device__ __forceinline__ float f2_lo(uint64_t v) {
    return __int_as_float((int)(v & 0xffffffffull));
}
__device__ __forceinline__ float f2_hi(uint64_t v) {
    return __int_as_float((int)(v >> 32));
}

// ---------------- scratch: device globals (no allocation allowed) -----------
__device__ float g_xz[(size_t)2 * NM * NG];      // 256 MB  input projections
__device__ float g_h [(size_t)NM * 2 * NH];      // 64 MB   concat h (fwd|bwd)
__device__ int   g_cnt[16];                      // [batch-slice][dir] counters
__device__ int   g_lens[NB];

// ---------------- math helpers ----------------------------------------------
__device__ __forceinline__ float sigf(float x) { return 1.f / (1.f + __expf(-x)); }
__device__ __forceinline__ float tanhf_fast(float x) {
    float e = __expf(2.f * fabsf(x));
    float t = 1.f - 2.f / (e + 1.f);
    return copysignf(t, x);
}

// ---------------- text lens --------------------------------------------------
__global__ void k_lens(const int* __restrict__ text) {
    int b = blockIdx.x;
    int c = 0;
    for (int i = threadIdx.x; i < NS; i += 128) c += (text[b * NS + i] != 0);
    #pragma unroll
    for (int o = 16; o; o >>= 1) c += __shfl_xor_sync(0xffffffffu, c, o);
    __shared__ int ws[4];
    if ((threadIdx.x & 31) == 0) ws[threadIdx.x >> 5] = c;
    __syncthreads();
    if (threadIdx.x == 0) g_lens[b] = ws[0] + ws[1] + ws[2] + ws[3];
}

// ---------------- barrier counter reset (each replay) ------------------------
__global__ void k_reset() { if (threadIdx.x < 16) g_cnt[threadIdx.x] = 0; }

// ---------------- xz = emb[text] @ W + b  (both dirs), FFMA2 ----------------
__global__ __launch_bounds__(256) void k_xz(
    const int* __restrict__ text, const float* __restrict__ emb,
    const float* __restrict__ Wf, const float* __restrict__ bf,
    const float* __restrict__ Wb, const float* __restrict__ bb)
{
    extern __shared__ float sm[];
    float* As = sm;               // 64 x 132
    float* Bs = sm + 64 * 132;    // 128 x 68
    __shared__ int tok[64];

    int t = threadIdx.x;
    int m0 = blockIdx.x * 64, n0 = blockIdx.y * 64, dir = blockIdx.z;
    const float* W    = dir ? Wb : Wf;
    const float* bias = dir ? bb : bf;

    if (t < 64) tok[t] = text[m0 + t];
    __syncthreads();

    #pragma unroll
    for (int i = 0; i < 8; i++) {
        int idx = t + i * 256;
        int r = idx >> 5, c4 = idx & 31;
        float4 v = reinterpret_cast<const float4*>(emb + (size_t)tok[r] * NE)[c4];
        *reinterpret_cast<float4*>(&As[r * 132 + c4 * 4]) = v;
    }
    #pragma unroll
    for (int i = 0; i < 32; i++) {
        int idx = t + i * 256;
        int k = idx >> 6, n = idx & 63;
        Bs[k * 68 + n] = W[(size_t)k * NG + n0 + n];
    }
    __syncthreads();

    int tx = t & 15, ty = t >> 4;
    uint64_t acc[4][2];
    #pragma unroll
    for (int j = 0; j < 4; j++) { acc[j][0] = 0ull; acc[j][1] = 0ull; }

    #pragma unroll 4
    for (int k0 = 0; k0 < 128; k0 += 4) {
        float av[4][4];
        #pragma unroll
        for (int j = 0; j < 4; j++)
            *reinterpret_cast<float4*>(av[j]) =
                *reinterpret_cast<const float4*>(&As[(ty * 4 + j) * 132 + k0]);
        #pragma unroll
        for (int kk = 0; kk < 4; kk++) {
            ulonglong2 b2 = *reinterpret_cast<const ulonglong2*>(&Bs[(k0 + kk) * 68 + tx * 4]);
            #pragma unroll
            for (int j = 0; j < 4; j++) {
                uint64_t ad; PACKDUP(ad, av[j][kk]);
                FMA2(acc[j][0], ad, b2.x);
                FMA2(acc[j][1], ad, b2.y);
            }
        }
    }

    float4 bv = *reinterpret_cast<const float4*>(bias + n0 + tx * 4);
    #pragma unroll
    for (int j = 0; j < 4; j++) {
        int m = m0 + ty * 4 + j;
        size_t base = ((size_t)dir * NM + m) * NG + n0 + tx * 4;
        float4 o;
        o.x = f2_lo(acc[j][0]) + bv.x;
        o.y = f2_hi(acc[j][0]) + bv.y;
        o.z = f2_lo(acc[j][1]) + bv.z;
        o.w = f2_hi(acc[j][1]) + bv.w;
        *reinterpret_cast<float4*>(&g_xz[base]) = o;
    }
}

// ---------------- persistent LSTM: U in registers, dual-dir interleaved ------
// grid (16 colblocks, 8 batch-slices) = 128 blocks, 256 threads, 1 CTA/SM
// (smem padded to 160KB). Each CTA: 16 h-cols (64 gate cols) x 8 batches,
// BOTH directions. U slices (both dirs) live in registers (128 regs/thread).
// Barrier group = 16 colblocks of one batch-slice; fwd barrier wait is hidden
// behind the bwd GEMM and vice versa.
__global__ __launch_bounds__(256) void k_lstm(const float* __restrict__ Uf,
                                              const float* __restrict__ Ub)
{
    extern __shared__ float sm[];
    float* hs = sm;            // [dir][bi][k] : 2*8*256 floats = 16KB
    float* zp = sm + 4096;     // [kq][bi][68] : 8*8*68 floats (padded)

    const int t   = threadIdx.x;
    const int cb  = blockIdx.x, bsl = blockIdx.y;
    const int j0  = cb * 16, b0 = bsl * 8;
    const int gid = bsl;

    // GEMM mapping: warp kq = 32-k slice; lane owns 2 cc (cc0, cc0+1)
    const int kq = t >> 5, lane = t & 31;
    const int cc0 = lane * 2;
    const int kbase = kq * 32;

    // gates mapping (t < 128): thread (gb, gj) owns h-col j0+gj of batch b0+gb
    const int gb = t >> 4, gj = t & 15;

    // ---- load U slices (both dirs) into registers -----------------------
    // u[d][k2][cc] = ( U[kbase+2*k2][col(cc0+cc)], U[kbase+2*k2+1][col(cc0+cc)] )
    uint64_t u[2][16][2];
    #pragma unroll
    for (int d = 0; d < 2; d++) {
        const float* U = d ? Ub : Uf;
        #pragma unroll
        for (int k2 = 0; k2 < 16; k2++) {
            int k = kbase + 2 * k2;
            #pragma unroll
            for (int cc = 0; cc < 2; cc++) {
                int c = cc0 + cc;
                int col = ((c >> 4) << 8) + j0 + (c & 15);
                float lo = U[(size_t)k * NG + col];
                float hi = U[(size_t)(k + 1) * NG + col];
                PACK2(u[d][k2][cc], lo, hi);
            }
        }
    }

    for (int i = t; i < 4096; i += 256) hs[i] = 0.f;
    __syncthreads();

    float c_reg[2] = {0.f, 0.f};
    int target = 0;

    for (int s = 0; s < NS; s++) {
        const int tmv[2] = { s, NS - 1 - s };
        target += 16;

        // prefetch xz for both dirs' gate phases (hidden under GEMMs)
        float xv[2][4];
        if (t < 128) {
            #pragma unroll
            for (int d = 0; d < 2; d++) {
                const float* xzp = g_xz +
                    (((size_t)d * NM + (size_t)(b0 + gb) * NS + tmv[d]) * NG + j0 + gj);
                xv[d][0] = xzp[0]; xv[d][1] = xzp[256];
                xv[d][2] = xzp[512]; xv[d][3] = xzp[768];
            }
        }

        #pragma unroll
        for (int d = 0; d < 2; d++) {
            const int tm = tmv[d];

            // ---- GEMM: acc[bi] pair = (even-k partial, odd-k partial) ----
            uint64_t acc[8][2];
            #pragma unroll
            for (int bi = 0; bi < 8; bi++) { acc[bi][0] = 0ull; acc[bi][1] = 0ull; }

            #pragma unroll
            for (int kk = 0; kk < 32; kk += 4) {
                const int k2 = kk >> 1;
                #pragma unroll
                for (int bi = 0; bi < 8; bi++) {
                    ulonglong2 hp = *reinterpret_cast<const ulonglong2*>(
                        &hs[d * 2048 + bi * 256 + kbase + kk]);
                    FMA2(acc[bi][0], hp.x, u[d][k2][0]);
                    FMA2(acc[bi][1], hp.x, u[d][k2][1]);
                    FMA2(acc[bi][0], hp.y, u[d][k2 + 1][0]);
                    FMA2(acc[bi][1], hp.y, u[d][k2 + 1][1]);
                }
            }
            #pragma unroll
            for (int bi = 0; bi < 8; bi++) {
                float2 v;
                v.x = f2_lo(acc[bi][0]) + f2_hi(acc[bi][0]);
                v.y = f2_lo(acc[bi][1]) + f2_hi(acc[bi][1]);
                *reinterpret_cast<float2*>(&zp[kq * 544 + bi * 68 + cc0]) = v;
            }
            __syncthreads();

            // ---- gates ----------------------------------------------------
            if (t < 128) {
                float zg4[4];
                #pragma unroll
                for (int g = 0; g < 4; g++) {
                    float zsum = xv[d][g];
                    #pragma unroll
                    for (int q = 0; q < 8; q++)
                        zsum += zp[q * 544 + gb * 68 + g * 16 + gj];
                    zg4[g] = zsum;
                }
                float ig = sigf(zg4[0]), fg = sigf(zg4[1]);
                float gg = tanhf_fast(zg4[2]), og = sigf(zg4[3]);
                c_reg[d] = fg * c_reg[d] + ig * gg;
                float hv = og * tanhf_fast(c_reg[d]);
                g_h[((size_t)(b0 + gb) * NS + tm) * (2 * NH) + d * NH + j0 + gj] = hv;
            }
            __syncthreads();   // gates' zp reads done; h STGs ordered before arrive

            if (t == 0 && s < NS - 1) {
                __threadfence();
                atomicAdd(&g_cnt[gid * 2 + d], 1);
            }
        }

        // ---- wait both barriers, then gather both dirs' full h -----------
        if (s < NS - 1) {
            if (t == 0) {
                while (*(volatile int*)&g_cnt[gid * 2 + 0] < target) { }
                while (*(volatile int*)&g_cnt[gid * 2 + 1] < target) { }
                __threadfence();
            }
            __syncthreads();
            #pragma unroll
            for (int j = 0; j < 4; j++) {
                int idx = t + j * 256;          // 0..1023 float4 slots
                int d  = idx >> 9;
                int r  = idx & 511;
                int bi = r >> 6, c4 = r & 63;
                float4 v = *reinterpret_cast<const float4*>(
                    g_h + ((size_t)(b0 + bi) * NS + tmv[d]) * (2 * NH) + d * NH + c4 * 4);
                *reinterpret_cast<float4*>(&hs[d * 2048 + bi * 256 + c4 * 4]) = v;
            }
            __syncthreads();
        }
    }
}

// ---------------- logits = h @ W_d + b_d -------------------------------------
__global__ __launch_bounds__(256) void k_logits(const float* __restrict__ Wd,
                                                const float* __restrict__ bd,
                                                float* __restrict__ out)
{
    __shared__ float Wd_s[512 * NT];
    __shared__ float bd_s[NT];
    int t = threadIdx.x;
    for (int i = t; i < 512 * NT; i += 256) Wd_s[i] = Wd[i];
    if (t < NT) bd_s[t] = bd[t];
    __syncthreads();

    int warp = t >> 5, lane = t & 31;
    size_t row = (size_t)blockIdx.x * 8 + warp;
    const float* hr = g_h + row * (2 * NH);

    float acc[NT];
    #pragma unroll
    for (int tg = 0; tg < NT; tg++) acc[tg] = 0.f;

    #pragma unroll
    for (int i = 0; i < 4; i++) {
        int kb = i * 128 + lane * 4;
        float4 h4 = *reinterpret_cast<const float4*>(hr + kb);
        float hvv[4] = {h4.x, h4.y, h4.z, h4.w};
        #pragma unroll
        for (int w = 0; w < 4; w++) {
            int k = kb + w;
            #pragma unroll
            for (int tg = 0; tg < NT; tg++) acc[tg] += hvv[w] * Wd_s[k * NT + tg];
        }
    }
    #pragma unroll
    for (int tg = 0; tg < NT; tg++)
        #pragma unroll
        for (int o = 16; o; o >>= 1) acc[tg] += __shfl_xor_sync(0xffffffffu, acc[tg], o);
    #pragma unroll
    for (int tg = 0; tg < NT; tg++)
        if (lane == tg) out[row * NT + tg] = acc[tg] + bd_s[tg];
}

// ---------------- CRF: sequence score & log-norm -----------------------------
__global__ void k_crf(const int* __restrict__ labels,
                      const float* __restrict__ trans,
                      float* __restrict__ out)
{
    int b = blockIdx.x, lane = threadIdx.x;
    int len = g_lens[b];
    const float* lg = out + (size_t)b * NS * NT;
    const int*   lb = labels + (size_t)b * NS;

    float sc = 0.f;
    for (int t = lane; t < len; t += 32)     sc += lg[t * NT + lb[t]];
    for (int t = lane; t + 1 < len; t += 32) sc += trans[lb[t] * NT + lb[t + 1]];
    #pragma unroll
    for (int o = 16; o; o >>= 1) sc += __shfl_xor_sync(0xffffffffu, sc, o);

    bool act = lane < NT;
    float tr[NT];
    #pragma unroll
    for (int i = 0; i < NT; i++) tr[i] = act ? trans[i * NT + lane] : 0.f;
    float alpha = act ? lg[lane] : -1e30f;

    for (int t = 1; t < len; t++) {
        float lgv = act ? lg[t * NT + lane] : 0.f;
        float v[NT]; float m = -1e30f;
        #pragma unroll
        for (int i = 0; i < NT; i++) {
            float ai = __shfl_sync(0xffffffffu, alpha, i);
            v[i] = ai + tr[i];
            m = fmaxf(m, v[i]);
        }
        float ssum = 0.f;
        #pragma unroll
        for (int i = 0; i < NT; i++) ssum += expf(v[i] - m);
        float na = m + logf(ssum) + lgv;
        if (act) alpha = na;
    }

    float m2 = act ? alpha : -1e30f;
    #pragma unroll
    for (int o = 16; o; o >>= 1) m2 = fmaxf(m2, __shfl_xor_sync(0xffffffffu, m2, o));
    float e = act ? expf(alpha - m2) : 0.f;
    #pragma unroll
    for (int o = 16; o; o >>= 1) e += __shfl_xor_sync(0xffffffffu, e, o);
    float lognorm = m2 + logf(e);

    if (lane == 0) {
        out[(size_t)NM * NT + b]      = (float)len;
        out[(size_t)NM * NT + NB + b] = sc - lognorm;
    }
}

// ---------------- launcher ----------------------------------------------------
extern "C" void kernel_launch(void* const* d_in, const int* in_sizes, int n_in,
                              void* d_out, int out_size)
{
    const int*   text   = (const int*)  d_in[0];
    const int*   labels = (const int*)  d_in[1];
    const float* emb    = (const float*)d_in[2];
    const float* Wf     = (const float*)d_in[3];
    const float* Uf     = (const float*)d_in[4];
    const float* bf     = (const float*)d_in[5];
    const float* Wb     = (const float*)d_in[6];
    const float* Ub     = (const float*)d_in[7];
    const float* bb     = (const float*)d_in[8];
    const float* Wd     = (const float*)d_in[9];
    const float* bd     = (const float*)d_in[10];
    const float* trans  = (const float*)d_in[11];
    float* out = (float*)d_out;

    const int XZ_SMEM   = (64 * 132 + 128 * 68) * 4;   // 68608 B
    const int LSTM_SMEM = 160 * 1024;                  // padded: force 1 CTA/SM
    cudaFuncSetAttribute(k_xz,   cudaFuncAttributeMaxDynamicSharedMemorySize, XZ_SMEM);
    cudaFuncSetAttribute(k_lstm, cudaFuncAttributeMaxDynamicSharedMemorySize, LSTM_SMEM);

    k_lens  <<<NB, 128>>>(text);
    k_reset <<<1, 32>>>();
    k_xz    <<<dim3(512, 16, 2), 256, XZ_SMEM>>>(text, emb, Wf, bf, Wb, bb);
    k_lstm  <<<dim3(16, 8, 1), 256, LSTM_SMEM>>>(Uf, Ub);
    k_logits<<<NM / 8, 256>>>(Wd, bd, out);
    k_crf   <<<NB, 32>>>(labels, trans, out);
}